// round 13
// baseline (speedup 1.0000x reference)
#include <cuda_runtime.h>
#include <math.h>
#include <stdint.h>

// Problem constants
#define B_     2
#define T_     16
#define S_     128
#define D_     512
#define H_     16
#define DH_    64
#define INNER_ 1024
#define NTOK   2048    // T_*S_
#define MROWS  4096    // B_*NTOK
#define HALF_XY 2097152   // MROWS*D_ elements per x/y plane
#define WSEG    524288    // 512*1024 elements per weight matrix

// Scratch (device globals)
__device__ float g_Q[MROWS * INNER_];
__device__ float g_K[MROWS * INNER_];
__device__ float g_V[MROWS * INNER_];
__device__ float g_O[MROWS * INNER_];   // xp|yp during qkv, then attn out
__device__ float g_W[4 * WSEG];         // tf32-rounded Wq|Wk|Wv|Wo
__device__ float g_wg[1032];            // wg2[1024], c at [1024]
__device__ float g_gate[MROWS];         // per-row gate value

// ---------------------------------------------------------------------------
// helpers
// ---------------------------------------------------------------------------
__device__ __forceinline__ uint32_t f2tf32(float f) {
    uint32_t u;
    asm("cvt.rna.tf32.f32 %0, %1;" : "=r"(u) : "f"(f));
    return u;
}

__device__ __forceinline__ void mma_tf32(float* c, const uint32_t* a,
                                         const uint32_t* b) {
    asm volatile(
        "mma.sync.aligned.m16n8k8.row.col.f32.tf32.tf32.f32 "
        "{%0,%1,%2,%3},{%4,%5,%6,%7},{%8,%9},{%0,%1,%2,%3};"
        : "+f"(c[0]), "+f"(c[1]), "+f"(c[2]), "+f"(c[3])
        : "r"(a[0]), "r"(a[1]), "r"(a[2]), "r"(a[3]), "r"(b[0]), "r"(b[1]));
}

__device__ __forceinline__ void cp16(uint32_t dst, const void* src) {
    asm volatile("cp.async.cg.shared.global [%0], [%1], 16;" :: "r"(dst), "l"(src));
}
__device__ __forceinline__ void cp_commit() {
    asm volatile("cp.async.commit_group;");
}
template<int N> __device__ __forceinline__ void cp_wait() {
    asm volatile("cp.async.wait_group %0;" :: "n"(N));
}

// ---------------------------------------------------------------------------
// prep kernels
// ---------------------------------------------------------------------------
__global__ void __launch_bounds__(256) prep_xy_kernel(
    const float* __restrict__ x, const float* __restrict__ y,
    const float* __restrict__ pos, float* __restrict__ xp,
    float* __restrict__ yp)
{
    int i = blockIdx.x * blockDim.x + threadIdx.x;
    int m = i >> 9;
    int d = i & 511;
    int t = (m & (NTOK - 1)) >> 7;
    float p = pos[t * D_ + d];
    xp[i] = __uint_as_float(f2tf32(x[i] + p));
    yp[i] = __uint_as_float(f2tf32(y[i] + p));
}

__global__ void __launch_bounds__(256) prep_w_kernel(
    const float* __restrict__ Wq, const float* __restrict__ Wk,
    const float* __restrict__ Wv, const float* __restrict__ Wo,
    float* __restrict__ Wc)
{
    int i = blockIdx.x * blockDim.x + threadIdx.x;
    int seg = i >> 19;
    int off = i & (WSEG - 1);
    const float* src = (seg == 0) ? Wq : (seg == 1) ? Wk : (seg == 2) ? Wv : Wo;
    Wc[i] = __uint_as_float(f2tf32(src[off]));
}

// wg2[k] = dot(Wo[k,:], gw)  (block per k, coalesced);  wg2[1024] = bo.gw + gb
__global__ void __launch_bounds__(128) prep_gate_kernel(
    const float* __restrict__ Wo, const float* __restrict__ bo,
    const float* __restrict__ gw, const float* __restrict__ gb,
    float* __restrict__ wg2)
{
    int k = blockIdx.x;            // 0..1024
    int tid = threadIdx.x;
    const float* src = (k < INNER_) ? (Wo + (size_t)k * D_) : bo;
    float part = 0.f;
#pragma unroll
    for (int r = 0; r < 4; r++) {
        int j = tid + r * 128;
        part += src[j] * gw[j];
    }
#pragma unroll
    for (int off = 16; off; off >>= 1)
        part += __shfl_xor_sync(0xffffffffu, part, off);
    __shared__ float red[4];
    if ((tid & 31) == 0) red[tid >> 5] = part;
    __syncthreads();
    if (tid == 0) {
        float tot = red[0] + red[1] + red[2] + red[3];
        wg2[k] = (k < INNER_) ? tot : (tot + gb[0]);
    }
}

// gate[m] = sigmoid(O_row . wg2 + c)
__global__ void __launch_bounds__(128) gatevec_kernel(
    const float* __restrict__ O, const float* __restrict__ wg2,
    float* __restrict__ gate)
{
    int m = blockIdx.x;
    int tid = threadIdx.x;
    const float* row = O + (size_t)m * INNER_;
    float part = 0.f;
#pragma unroll
    for (int r = 0; r < 8; r++) {
        int j = tid + r * 128;
        part += row[j] * wg2[j];
    }
#pragma unroll
    for (int off = 16; off; off >>= 1)
        part += __shfl_xor_sync(0xffffffffu, part, off);
    __shared__ float red[4];
    if ((tid & 31) == 0) red[tid >> 5] = part;
    __syncthreads();
    if (tid == 0) {
        float tot = red[0] + red[1] + red[2] + red[3] + wg2[INNER_];
        gate[m] = 1.f / (1.f + __expf(-tot));
    }
}

// ---------------------------------------------------------------------------
// GEMM v3 (R8 structure): CTA 128x128, 4 warps of 64x64, BK=32, 2-stage
// cp.async. MODE 0: qkv (V tf32-rounded; Q/K fp32, rope kernel rounds).
// MODE 1: proj: (acc + bias) * gate[row] -> out (fp32).
// ---------------------------------------------------------------------------
#define G_ASTR 36
#define G_BSTR 136
#define G_A0   0
#define G_A1   4608
#define G_B0   9216
#define G_B1   13568
#define G_SMEM_BYTES (17920 * 4)

template<int KDIM, int NDIM, int MODE>
__global__ void __launch_bounds__(128, 2) gemm3_kernel(
    const float* __restrict__ Abase, const float* __restrict__ Wbase,
    float* __restrict__ C0, float* __restrict__ C1, float* __restrict__ C2,
    const float* __restrict__ bias, const float* __restrict__ gate)
{
    extern __shared__ uint32_t dsm[];

    const float* A;
    const float* W;
    float* C;
    int z = 0;
    if (MODE == 0) {
        z = blockIdx.z;
        A = Abase + ((z == 2) ? HALF_XY : 0);
        W = Wbase + z * WSEG;
        C = (z == 0) ? C0 : (z == 1) ? C1 : C2;
    } else {
        A = Abase; W = Wbase; C = C0;
    }

    int tid   = threadIdx.x;
    int lane  = tid & 31;
    int warp  = tid >> 5;
    int warpM = warp >> 1;
    int warpN = warp & 1;
    int m0 = blockIdx.y * 128;
    int n0 = blockIdx.x * 128;

    uint32_t smBase = (uint32_t)__cvta_generic_to_shared(dsm);
    uint32_t aOff[2] = {smBase + G_A0 * 4, smBase + G_A1 * 4};
    uint32_t bOff[2] = {smBase + G_B0 * 4, smBase + G_B1 * 4};

    const int NS = KDIM / 32;

    auto load_slab = [&](int s, int buf) {
#pragma unroll
        for (int i = 0; i < 8; i++) {
            int q = tid + i * 128;
            int ar = q >> 3, ac = (q & 7) * 4;
            cp16(aOff[buf] + (uint32_t)(ar * G_ASTR + ac) * 4,
                 A + (size_t)(m0 + ar) * KDIM + s * 32 + ac);
            int br = q >> 5, bc = (q & 31) * 4;
            cp16(bOff[buf] + (uint32_t)(br * G_BSTR + bc) * 4,
                 W + (size_t)(s * 32 + br) * NDIM + n0 + bc);
        }
        cp_commit();
    };

    float acc[4][8][4];
#pragma unroll
    for (int mt = 0; mt < 4; mt++)
#pragma unroll
        for (int nt = 0; nt < 8; nt++)
#pragma unroll
            for (int e = 0; e < 4; e++) acc[mt][nt][e] = 0.f;

    load_slab(0, 0);

    for (int s = 0; s < NS; s++) {
        int buf = s & 1;
        if (s + 1 < NS) {
            load_slab(s + 1, buf ^ 1);
            cp_wait<1>();
        } else {
            cp_wait<0>();
        }
        __syncthreads();

        const uint32_t* uA = dsm + (buf ? G_A1 : G_A0);
        const uint32_t* uB = dsm + (buf ? G_B1 : G_B0);
#pragma unroll
        for (int ks = 0; ks < 4; ks++) {
            uint32_t af[4][4];
#pragma unroll
            for (int mt = 0; mt < 4; mt++) {
                int r0 = warpM * 64 + mt * 16 + (lane >> 2);
                int c  = ks * 8 + (lane & 3);
                af[mt][0] = uA[r0 * G_ASTR + c];
                af[mt][1] = uA[(r0 + 8) * G_ASTR + c];
                af[mt][2] = uA[r0 * G_ASTR + c + 4];
                af[mt][3] = uA[(r0 + 8) * G_ASTR + c + 4];
            }
            uint32_t bf[8][2];
#pragma unroll
            for (int nt = 0; nt < 8; nt++) {
                int n = warpN * 64 + nt * 8 + (lane >> 2);
                int k = ks * 8 + (lane & 3);
                bf[nt][0] = uB[k * G_BSTR + n];
                bf[nt][1] = uB[(k + 4) * G_BSTR + n];
            }
#pragma unroll
            for (int mt = 0; mt < 4; mt++)
#pragma unroll
                for (int nt = 0; nt < 8; nt++)
                    mma_tf32(acc[mt][nt], af[mt], bf[nt]);
        }
        __syncthreads();
    }

#pragma unroll
    for (int mt = 0; mt < 4; mt++) {
#pragma unroll
        for (int nt = 0; nt < 8; nt++) {
            int row = m0 + warpM * 64 + mt * 16 + (lane >> 2);
            int col = n0 + warpN * 64 + nt * 8 + 2 * (lane & 3);
            if (MODE == 1) {
                float b0 = bias[col], b1 = bias[col + 1];
                float g0 = gate[row], g8 = gate[row + 8];
                *(float2*)(C + (size_t)row * NDIM + col) =
                    make_float2((acc[mt][nt][0] + b0) * g0,
                                (acc[mt][nt][1] + b1) * g0);
                *(float2*)(C + (size_t)(row + 8) * NDIM + col) =
                    make_float2((acc[mt][nt][2] + b0) * g8,
                                (acc[mt][nt][3] + b1) * g8);
            } else if (z == 2) {
                *(uint2*)(C + (size_t)row * NDIM + col) =
                    make_uint2(f2tf32(acc[mt][nt][0]), f2tf32(acc[mt][nt][1]));
                *(uint2*)(C + (size_t)(row + 8) * NDIM + col) =
                    make_uint2(f2tf32(acc[mt][nt][2]), f2tf32(acc[mt][nt][3]));
            } else {
                *(float2*)(C + (size_t)row * NDIM + col) =
                    make_float2(acc[mt][nt][0], acc[mt][nt][1]);
                *(float2*)(C + (size_t)(row + 8) * NDIM + col) =
                    make_float2(acc[mt][nt][2], acc[mt][nt][3]);
            }
        }
    }
}

// ---------------------------------------------------------------------------
// RoPE in-place on Q and K; writes tf32-rounded values.
// ---------------------------------------------------------------------------
__global__ void __launch_bounds__(256) rope_kernel(float* __restrict__ Q,
                                                   float* __restrict__ Kt)
{
    int gid = blockIdx.x * blockDim.x + threadIdx.x;
    int m  = gid >> 9;
    int r  = gid & 511;
    int h  = r >> 5;
    int dd = r & 31;
    int i  = m & (NTOK - 1);

    float inv = exp2f(-(float)dd * (13.287712379549449f / 32.0f));
    float f = (float)i * inv;
    float c = cosf(f), s = sinf(f);

    size_t base = (size_t)m * INNER_ + h * DH_ + dd;
    float a = Q[base], b2 = Q[base + 32];
    Q[base]      = __uint_as_float(f2tf32(a * c - b2 * s));
    Q[base + 32] = __uint_as_float(f2tf32(b2 * c + a * s));
    a = Kt[base]; b2 = Kt[base + 32];
    Kt[base]      = __uint_as_float(f2tf32(a * c - b2 * s));
    Kt[base + 32] = __uint_as_float(f2tf32(b2 * c + a * s));
}

// ---------------------------------------------------------------------------
// Flash attention v2 (R8 structure): 64-key chunks, cp.async K/V loads.
// smem words: K@0 (64x68), V@4352 (64x72), P@8960 (4x32x68); 17664 words.
// ---------------------------------------------------------------------------
#define A_KOFF 0
#define A_VOFF 4352
#define A_POFF 8960
#define A_KSTR 68
#define A_VSTR 72
#define A_PSTR 68
#define A_QSTR 68
#define A_SMEM_BYTES (17664 * 4)

__global__ void __launch_bounds__(128, 2) attn_mma_kernel(
    const float* __restrict__ Q, const float* __restrict__ K,
    const float* __restrict__ V, const int* __restrict__ tmask,
    float* __restrict__ O)
{
    extern __shared__ uint32_t sm[];

    int blk  = blockIdx.x;
    int ti   = blk % T_;
    int bh   = blk / T_;
    int h    = bh % H_;
    int b    = bh / H_;
    int tid  = threadIdx.x;
    int lane = tid & 31;
    int warp = tid >> 5;

    uint32_t smBase = (uint32_t)__cvta_generic_to_shared(sm);

    // stage Q tile 128x64 (raw bits already tf32); reuses K+V region
    {
        const float* qg = Q + ((size_t)(b * NTOK + ti * S_)) * INNER_ + h * DH_;
#pragma unroll
        for (int i = 0; i < 16; i++) {
            int idx = tid + i * 128;
            int row = idx >> 4, c4 = (idx & 15) * 4;
            float4 v4 = *(const float4*)(qg + (size_t)row * INNER_ + c4);
            *(uint4*)&sm[row * A_QSTR + c4] =
                make_uint4(__float_as_uint(v4.x), __float_as_uint(v4.y),
                           __float_as_uint(v4.z), __float_as_uint(v4.w));
        }
    }
    __syncthreads();

    uint32_t qf[2][8][4];
#pragma unroll
    for (int mt = 0; mt < 2; mt++)
#pragma unroll
        for (int kt = 0; kt < 8; kt++) {
            int r0 = warp * 32 + mt * 16 + (lane >> 2);
            int c  = kt * 8 + (lane & 3);
            qf[mt][kt][0] = sm[r0 * A_QSTR + c];
            qf[mt][kt][1] = sm[(r0 + 8) * A_QSTR + c];
            qf[mt][kt][2] = sm[r0 * A_QSTR + c + 4];
            qf[mt][kt][3] = sm[(r0 + 8) * A_QSTR + c + 4];
        }

    float of[2][8][4];
#pragma unroll
    for (int mt = 0; mt < 2; mt++)
#pragma unroll
        for (int nt = 0; nt < 8; nt++)
#pragma unroll
            for (int e = 0; e < 4; e++) of[mt][nt][e] = 0.f;
    float mx[2][2]  = {{-1e30f, -1e30f}, {-1e30f, -1e30f}};
    float ell[2][2] = {{0.f, 0.f}, {0.f, 0.f}};

    uint32_t pw = A_POFF + warp * (32 * A_PSTR);

    for (int tj = 0; tj < T_; tj++) {
        if (tmask[(b * T_ + ti) * T_ + tj] == 0) continue;
#pragma unroll 1
        for (int half = 0; half < 2; half++) {
            int j0 = tj * S_ + half * 64;
            const float* kb = K + ((size_t)(b * NTOK + j0)) * INNER_ + h * DH_;
            const float* vb = V + ((size_t)(b * NTOK + j0)) * INNER_ + h * DH_;
            __syncthreads();     // previous chunk's reads done
            // K and V tiles: 64 rows x 16 float4-chunks = 1024 chunks EACH
#pragma unroll
            for (int i = 0; i < 8; i++) {
                int q = tid + i * 128;        // 0..1023
                int row = q >> 4, c4 = (q & 15) * 4;
                cp16(smBase + (uint32_t)(A_KOFF + row * A_KSTR + c4) * 4,
                     kb + (size_t)row * INNER_ + c4);
                cp16(smBase + (uint32_t)(A_VOFF + row * A_VSTR + c4) * 4,
                     vb + (size_t)row * INNER_ + c4);
            }
            cp_commit();
            cp_wait<0>();
            __syncthreads();

            // S = Q * K^T (32 rows x 64 keys per warp)
            float sf[2][8][4];
#pragma unroll
            for (int mt = 0; mt < 2; mt++)
#pragma unroll
                for (int nt = 0; nt < 8; nt++)
#pragma unroll
                    for (int e = 0; e < 4; e++) sf[mt][nt][e] = 0.f;

#pragma unroll
            for (int kt = 0; kt < 8; kt++) {
                uint32_t bfr[8][2];
#pragma unroll
                for (int nt = 0; nt < 8; nt++) {
                    int n = nt * 8 + (lane >> 2);
                    int c = kt * 8 + (lane & 3);
                    bfr[nt][0] = sm[A_KOFF + n * A_KSTR + c];
                    bfr[nt][1] = sm[A_KOFF + n * A_KSTR + c + 4];
                }
#pragma unroll
                for (int mt = 0; mt < 2; mt++)
#pragma unroll
                    for (int nt = 0; nt < 8; nt++)
                        mma_tf32(sf[mt][nt], qf[mt][kt], bfr[nt]);
            }

            // online softmax over 64 keys
#pragma unroll
            for (int mt = 0; mt < 2; mt++) {
#pragma unroll
                for (int hh = 0; hh < 2; hh++) {
                    float cm = -1e30f;
#pragma unroll
                    for (int nt = 0; nt < 8; nt++) {
                        float s0 = sf[mt][nt][2 * hh]     * 0.125f;
                        float s1 = sf[mt][nt][2 * hh + 1] * 0.125f;
                        sf[mt][nt][2 * hh]     = s0;
                        sf[mt][nt][2 * hh + 1] = s1;
                        cm = fmaxf(cm, fmaxf(s0, s1));
                    }
                    cm = fmaxf(cm, __shfl_xor_sync(0xffffffffu, cm, 1));
                    cm = fmaxf(cm, __shfl_xor_sync(0xffffffffu, cm, 2));
                    float nm = fmaxf(mx[mt][hh], cm);
                    float corr = __expf(mx[mt][hh] - nm);
                    mx[mt][hh] = nm;
                    ell[mt][hh] *= corr;
#pragma unroll
                    for (int nt = 0; nt < 8; nt++) {
                        of[mt][nt][2 * hh]     *= corr;
                        of[mt][nt][2 * hh + 1] *= corr;
                    }
                    float rs = 0.f;
                    int rloc = mt * 16 + (lane >> 2) + hh * 8;
#pragma unroll
                    for (int nt = 0; nt < 8; nt++) {
                        float p0 = __expf(sf[mt][nt][2 * hh]     - nm);
                        float p1 = __expf(sf[mt][nt][2 * hh + 1] - nm);
                        rs += p0 + p1;
                        *(uint2*)&sm[pw + rloc * A_PSTR + nt * 8 + 2 * (lane & 3)] =
                            make_uint2(f2tf32(p0), f2tf32(p1));
                    }
                    rs += __shfl_xor_sync(0xffffffffu, rs, 1);
                    rs += __shfl_xor_sync(0xffffffffu, rs, 2);
                    ell[mt][hh] += rs;
                }
            }
            __syncwarp();

            // O += P * V (P: 32x64, V: 64x64)
#pragma unroll
            for (int kt = 0; kt < 8; kt++) {
                uint32_t pf[2][4];
#pragma unroll
                for (int mt = 0; mt < 2; mt++) {
                    int r0 = mt * 16 + (lane >> 2);
                    int c  = kt * 8 + (lane & 3);
                    pf[mt][0] = sm[pw + r0 * A_PSTR + c];
                    pf[mt][1] = sm[pw + (r0 + 8) * A_PSTR + c];
                    pf[mt][2] = sm[pw + r0 * A_PSTR + c + 4];
                    pf[mt][3] = sm[pw + (r0 + 8) * A_PSTR + c + 4];
                }
                uint32_t vf[8][2];
#pragma unroll
                for (int nt = 0; nt < 8; nt++) {
                    int n = nt * 8 + (lane >> 2);
                    int k = kt * 8 + (lane & 3);
                    vf[nt][0] = sm[A_VOFF + k * A_VSTR + n];
                    vf[nt][1] = sm[A_VOFF + (k + 4) * A_VSTR + n];
                }
#pragma unroll
                for (int mt = 0; mt < 2; mt++)
#pragma unroll
                    for (int nt = 0; nt < 8; nt++)
                        mma_tf32(of[mt][nt], pf[mt], vf[nt]);
            }
            __syncwarp();
        }
    }

    // normalize + tf32-round + write
#pragma unroll
    for (int mt = 0; mt < 2; mt++) {
#pragma unroll
        for (int hh = 0; hh < 2; hh++) {
            float inv = (ell[mt][hh] > 0.f) ? (1.f / ell[mt][hh]) : 0.f;
            int row = b * NTOK + ti * S_ + warp * 32 + mt * 16 + (lane >> 2) + hh * 8;
#pragma unroll
            for (int nt = 0; nt < 8; nt++) {
                int col = h * DH_ + nt * 8 + 2 * (lane & 3);
                *(uint2*)(O + (size_t)row * INNER_ + col) =
                    make_uint2(f2tf32(of[mt][nt][2 * hh] * inv),
                               f2tf32(of[mt][nt][2 * hh + 1] * inv));
            }
        }
    }
}

// ---------------------------------------------------------------------------
extern "C" void kernel_launch(void* const* d_in, const int* in_sizes, int n_in,
                              void* d_out, int out_size)
{
    (void)in_sizes; (void)n_in; (void)out_size;
    const float* x     = (const float*)d_in[0];
    const float* y     = (const float*)d_in[1];
    const int*   tmask = (const int*)  d_in[2];
    const float* Wq    = (const float*)d_in[3];
    const float* Wk    = (const float*)d_in[4];
    const float* Wv    = (const float*)d_in[5];
    const float* Wo    = (const float*)d_in[6];
    const float* bo    = (const float*)d_in[7];
    const float* pos   = (const float*)d_in[8];
    const float* gw    = (const float*)d_in[9];
    const float* gb    = (const float*)d_in[10];
    float* out = (float*)d_out;

    float *Qp, *Kp, *Vp, *Op, *Wc, *wg2, *gate;
    cudaGetSymbolAddress((void**)&Qp, g_Q);
    cudaGetSymbolAddress((void**)&Kp, g_K);
    cudaGetSymbolAddress((void**)&Vp, g_V);
    cudaGetSymbolAddress((void**)&Op, g_O);
    cudaGetSymbolAddress((void**)&Wc, g_W);
    cudaGetSymbolAddress((void**)&wg2, g_wg);
    cudaGetSymbolAddress((void**)&gate, g_gate);

    cudaFuncSetAttribute(gemm3_kernel<D_, INNER_, 0>,
                         cudaFuncAttributeMaxDynamicSharedMemorySize, G_SMEM_BYTES);
    cudaFuncSetAttribute(gemm3_kernel<INNER_, D_, 1>,
                         cudaFuncAttributeMaxDynamicSharedMemorySize, G_SMEM_BYTES);
    cudaFuncSetAttribute(attn_mma_kernel,
                         cudaFuncAttributeMaxDynamicSharedMemorySize, A_SMEM_BYTES);

    prep_xy_kernel<<<HALF_XY / 256, 256>>>(x, y, pos, Op, Op + HALF_XY);
    prep_w_kernel<<<(4 * WSEG) / 256, 256>>>(Wq, Wk, Wv, Wo, Wc);
    prep_gate_kernel<<<INNER_ + 1, 128>>>(Wo, bo, gw, gb, wg2);

    // QKV: [4096,1024] = xp/yp @ Wq/Wk/Wv
    dim3 gq(INNER_ / 128, MROWS / 128, 3);     // 8 x 32 x 3
    gemm3_kernel<D_, INNER_, 0><<<gq, 128, G_SMEM_BYTES>>>(
        Op, Wc, Qp, Kp, Vp, nullptr, nullptr);

    rope_kernel<<<(MROWS * 512) / 256, 256>>>(Qp, Kp);

    attn_mma_kernel<<<B_ * H_ * T_, 128, A_SMEM_BYTES>>>(Qp, Kp, Vp, tmask, Op);

    gatevec_kernel<<<MROWS, 128>>>(Op, wg2, gate);

    // Proj (+bias, +gate): out[4096,512] = (O @ Wo + bo) * gate
    dim3 gp(D_ / 128, MROWS / 128, 1);         // 4 x 32
    gemm3_kernel<INNER_, D_, 1><<<gp, 128, G_SMEM_BYTES>>>(
        Op, Wc + 3 * WSEG, out, nullptr, nullptr, bo, gate);
}

// round 16
// speedup vs baseline: 1.0209x; 1.0209x over previous
#include <cuda_runtime.h>
#include <math.h>
#include <stdint.h>

// Problem constants
#define B_     2
#define T_     16
#define S_     128
#define D_     512
#define H_     16
#define DH_    64
#define INNER_ 1024
#define NTOK   2048    // T_*S_
#define MROWS  4096    // B_*NTOK
#define HALF_XY 2097152   // MROWS*D_ elements per x/y plane
#define WSEG    524288    // 512*1024 elements per weight matrix

// Scratch (device globals)
__device__ float g_Q[MROWS * INNER_];
__device__ float g_K[MROWS * INNER_];
__device__ float g_V[MROWS * INNER_];
__device__ float g_O[MROWS * INNER_];   // xp|yp during qkv, then attn out
__device__ float g_P[MROWS * D_];       // output projection result
__device__ float g_W[4 * WSEG];         // tf32-rounded Wq|Wk|Wv|Wo
__device__ float2 g_rope[NTOK * 32];    // (cos,sin) per (pos, freq)

// ---------------------------------------------------------------------------
// helpers
// ---------------------------------------------------------------------------
__device__ __forceinline__ uint32_t f2tf32(float f) {
    uint32_t u;
    asm("cvt.rna.tf32.f32 %0, %1;" : "=r"(u) : "f"(f));
    return u;
}

__device__ __forceinline__ void mma_tf32(float* c, const uint32_t* a,
                                         const uint32_t* b) {
    asm volatile(
        "mma.sync.aligned.m16n8k8.row.col.f32.tf32.tf32.f32 "
        "{%0,%1,%2,%3},{%4,%5,%6,%7},{%8,%9},{%0,%1,%2,%3};"
        : "+f"(c[0]), "+f"(c[1]), "+f"(c[2]), "+f"(c[3])
        : "r"(a[0]), "r"(a[1]), "r"(a[2]), "r"(a[3]), "r"(b[0]), "r"(b[1]));
}

__device__ __forceinline__ void cp16(uint32_t dst, const void* src) {
    asm volatile("cp.async.cg.shared.global [%0], [%1], 16;" :: "r"(dst), "l"(src));
}
__device__ __forceinline__ void cp_commit() {
    asm volatile("cp.async.commit_group;");
}
template<int N> __device__ __forceinline__ void cp_wait() {
    asm volatile("cp.async.wait_group %0;" :: "n"(N));
}

#define ROPE_C (13.287712379549449f / 32.0f)

// ---------------------------------------------------------------------------
// prep kernels
// ---------------------------------------------------------------------------
__global__ void __launch_bounds__(256) prep_xy_kernel(
    const float* __restrict__ x, const float* __restrict__ y,
    const float* __restrict__ pos, float* __restrict__ xp,
    float* __restrict__ yp)
{
    int i = blockIdx.x * blockDim.x + threadIdx.x;
    int m = i >> 9;
    int d = i & 511;
    int t = (m & (NTOK - 1)) >> 7;
    float p = pos[t * D_ + d];
    xp[i] = __uint_as_float(f2tf32(x[i] + p));
    yp[i] = __uint_as_float(f2tf32(y[i] + p));
}

__global__ void __launch_bounds__(256) prep_w_kernel(
    const float* __restrict__ Wq, const float* __restrict__ Wk,
    const float* __restrict__ Wv, const float* __restrict__ Wo,
    float* __restrict__ Wc)
{
    int i = blockIdx.x * blockDim.x + threadIdx.x;
    int seg = i >> 19;
    int off = i & (WSEG - 1);
    const float* src = (seg == 0) ? Wq : (seg == 1) ? Wk : (seg == 2) ? Wv : Wo;
    Wc[i] = __uint_as_float(f2tf32(src[off]));
}

// rope table: (cos,sin) for position i, freq dd (same formula as old rope kernel)
__global__ void __launch_bounds__(256) prep_rope_kernel(float2* __restrict__ tab)
{
    int idx = blockIdx.x * blockDim.x + threadIdx.x;   // [0, NTOK*32)
    int i  = idx >> 5;
    int dd = idx & 31;
    float inv = exp2f(-(float)dd * ROPE_C);
    float f = (float)i * inv;
    tab[idx] = make_float2(cosf(f), sinf(f));
}

// ---------------------------------------------------------------------------
// GEMM v3: CTA 128x128, 4 warps of 64x64, BK=32, 2-stage cp.async.
// MODE 0 (qkv): z selects input/weight/output. z<2 (Q/K): fused table-RoPE
//   in the epilogue, then tf32-rounded store. z=2 (V): tf32-rounded store.
// MODE 1 (proj): acc + bias -> g_P (fp32).
// ---------------------------------------------------------------------------
#define G_ASTR 36
#define G_BSTR 136
#define G_A0   0
#define G_A1   4608
#define G_B0   9216
#define G_B1   13568
#define G_SMEM_BYTES (17920 * 4)

template<int KDIM, int NDIM, int MODE>
__global__ void __launch_bounds__(128, 2) gemm3_kernel(
    const float* __restrict__ Abase, const float* __restrict__ Wbase,
    float* __restrict__ C0, float* __restrict__ C1, float* __restrict__ C2,
    const float* __restrict__ bias, const float2* __restrict__ rope)
{
    extern __shared__ uint32_t dsm[];

    const float* A;
    const float* W;
    float* C;
    int z = 0;
    if (MODE == 0) {
        z = blockIdx.z;
        A = Abase + ((z == 2) ? HALF_XY : 0);
        W = Wbase + z * WSEG;
        C = (z == 0) ? C0 : (z == 1) ? C1 : C2;
    } else {
        A = Abase; W = Wbase; C = C0;
    }

    int tid   = threadIdx.x;
    int lane  = tid & 31;
    int warp  = tid >> 5;
    int warpM = warp >> 1;
    int warpN = warp & 1;
    int m0 = blockIdx.y * 128;
    int n0 = blockIdx.x * 128;

    uint32_t smBase = (uint32_t)__cvta_generic_to_shared(dsm);
    uint32_t aOff[2] = {smBase + G_A0 * 4, smBase + G_A1 * 4};
    uint32_t bOff[2] = {smBase + G_B0 * 4, smBase + G_B1 * 4};

    const int NS = KDIM / 32;

    auto load_slab = [&](int s, int buf) {
#pragma unroll
        for (int i = 0; i < 8; i++) {
            int q = tid + i * 128;
            int ar = q >> 3, ac = (q & 7) * 4;
            cp16(aOff[buf] + (uint32_t)(ar * G_ASTR + ac) * 4,
                 A + (size_t)(m0 + ar) * KDIM + s * 32 + ac);
            int br = q >> 5, bc = (q & 31) * 4;
            cp16(bOff[buf] + (uint32_t)(br * G_BSTR + bc) * 4,
                 W + (size_t)(s * 32 + br) * NDIM + n0 + bc);
        }
        cp_commit();
    };

    float acc[4][8][4];
#pragma unroll
    for (int mt = 0; mt < 4; mt++)
#pragma unroll
        for (int nt = 0; nt < 8; nt++)
#pragma unroll
            for (int e = 0; e < 4; e++) acc[mt][nt][e] = 0.f;

    load_slab(0, 0);

    for (int s = 0; s < NS; s++) {
        int buf = s & 1;
        if (s + 1 < NS) {
            load_slab(s + 1, buf ^ 1);
            cp_wait<1>();
        } else {
            cp_wait<0>();
        }
        __syncthreads();

        const uint32_t* uA = dsm + (buf ? G_A1 : G_A0);
        const uint32_t* uB = dsm + (buf ? G_B1 : G_B0);
#pragma unroll
        for (int ks = 0; ks < 4; ks++) {
            uint32_t af[4][4];
#pragma unroll
            for (int mt = 0; mt < 4; mt++) {
                int r0 = warpM * 64 + mt * 16 + (lane >> 2);
                int c  = ks * 8 + (lane & 3);
                af[mt][0] = uA[r0 * G_ASTR + c];
                af[mt][1] = uA[(r0 + 8) * G_ASTR + c];
                af[mt][2] = uA[r0 * G_ASTR + c + 4];
                af[mt][3] = uA[(r0 + 8) * G_ASTR + c + 4];
            }
            uint32_t bf[8][2];
#pragma unroll
            for (int nt = 0; nt < 8; nt++) {
                int n = warpN * 64 + nt * 8 + (lane >> 2);
                int k = ks * 8 + (lane & 3);
                bf[nt][0] = uB[k * G_BSTR + n];
                bf[nt][1] = uB[(k + 4) * G_BSTR + n];
            }
#pragma unroll
            for (int mt = 0; mt < 4; mt++)
#pragma unroll
                for (int nt = 0; nt < 8; nt++)
                    mma_tf32(acc[mt][nt], af[mt], bf[nt]);
        }
        __syncthreads();
    }

    // ---- fused table-RoPE for Q/K (z<2). Column d (in [0,32) of the head)
    // pairs with d+32 = acc[mt][nt+4]; rotation values from the table
    // (identical cosf/sinf to the old rope kernel). Mapping validated in R10.
    if (MODE == 0 && z < 2) {
#pragma unroll
        for (int mt = 0; mt < 4; mt++) {
            int row = m0 + warpM * 64 + mt * 16 + (lane >> 2);
            int i0 = row & (NTOK - 1);
            int i1 = (row + 8) & (NTOK - 1);
#pragma unroll
            for (int nt = 0; nt < 4; nt++) {
                int d0 = nt * 8 + 2 * (lane & 3);
                float4 cs0 = *(const float4*)&rope[i0 * 32 + d0]; // c0,s0,c1,s1
                float4 cs1 = *(const float4*)&rope[i1 * 32 + d0];
                float a, bb;
                a = acc[mt][nt][0]; bb = acc[mt][nt + 4][0];
                acc[mt][nt][0]     = a * cs0.x - bb * cs0.y;
                acc[mt][nt + 4][0] = bb * cs0.x + a * cs0.y;
                a = acc[mt][nt][1]; bb = acc[mt][nt + 4][1];
                acc[mt][nt][1]     = a * cs0.z - bb * cs0.w;
                acc[mt][nt + 4][1] = bb * cs0.z + a * cs0.w;
                a = acc[mt][nt][2]; bb = acc[mt][nt + 4][2];
                acc[mt][nt][2]     = a * cs1.x - bb * cs1.y;
                acc[mt][nt + 4][2] = bb * cs1.x + a * cs1.y;
                a = acc[mt][nt][3]; bb = acc[mt][nt + 4][3];
                acc[mt][nt][3]     = a * cs1.z - bb * cs1.w;
                acc[mt][nt + 4][3] = bb * cs1.z + a * cs1.w;
            }
        }
    }

#pragma unroll
    for (int mt = 0; mt < 4; mt++) {
#pragma unroll
        for (int nt = 0; nt < 8; nt++) {
            int row = m0 + warpM * 64 + mt * 16 + (lane >> 2);
            int col = n0 + warpN * 64 + nt * 8 + 2 * (lane & 3);
            if (MODE == 1) {
                float b0 = bias[col], b1 = bias[col + 1];
                *(float2*)(C + (size_t)row * NDIM + col) =
                    make_float2(acc[mt][nt][0] + b0, acc[mt][nt][1] + b1);
                *(float2*)(C + (size_t)(row + 8) * NDIM + col) =
                    make_float2(acc[mt][nt][2] + b0, acc[mt][nt][3] + b1);
            } else {
                // Q/K (rotated) and V all stored tf32-rounded for the attn mma
                *(uint2*)(C + (size_t)row * NDIM + col) =
                    make_uint2(f2tf32(acc[mt][nt][0]), f2tf32(acc[mt][nt][1]));
                *(uint2*)(C + (size_t)(row + 8) * NDIM + col) =
                    make_uint2(f2tf32(acc[mt][nt][2]), f2tf32(acc[mt][nt][3]));
            }
        }
    }
}

// ---------------------------------------------------------------------------
// Flash attention v2 (R8 structure): 64-key chunks, cp.async K/V loads.
// smem words: K@0 (64x68), V@4352 (64x72), P@8960 (4x32x68); 17664 words.
// ---------------------------------------------------------------------------
#define A_KOFF 0
#define A_VOFF 4352
#define A_POFF 8960
#define A_KSTR 68
#define A_VSTR 72
#define A_PSTR 68
#define A_QSTR 68
#define A_SMEM_BYTES (17664 * 4)

__global__ void __launch_bounds__(128, 2) attn_mma_kernel(
    const float* __restrict__ Q, const float* __restrict__ K,
    const float* __restrict__ V, const int* __restrict__ tmask,
    float* __restrict__ O)
{
    extern __shared__ uint32_t sm[];

    int blk  = blockIdx.x;
    int ti   = blk % T_;
    int bh   = blk / T_;
    int h    = bh % H_;
    int b    = bh / H_;
    int tid  = threadIdx.x;
    int lane = tid & 31;
    int warp = tid >> 5;

    uint32_t smBase = (uint32_t)__cvta_generic_to_shared(sm);

    // stage Q tile 128x64 (raw bits already tf32); reuses K+V region
    {
        const float* qg = Q + ((size_t)(b * NTOK + ti * S_)) * INNER_ + h * DH_;
#pragma unroll
        for (int i = 0; i < 16; i++) {
            int idx = tid + i * 128;
            int row = idx >> 4, c4 = (idx & 15) * 4;
            float4 v4 = *(const float4*)(qg + (size_t)row * INNER_ + c4);
            *(uint4*)&sm[row * A_QSTR + c4] =
                make_uint4(__float_as_uint(v4.x), __float_as_uint(v4.y),
                           __float_as_uint(v4.z), __float_as_uint(v4.w));
        }
    }
    __syncthreads();

    uint32_t qf[2][8][4];
#pragma unroll
    for (int mt = 0; mt < 2; mt++)
#pragma unroll
        for (int kt = 0; kt < 8; kt++) {
            int r0 = warp * 32 + mt * 16 + (lane >> 2);
            int c  = kt * 8 + (lane & 3);
            qf[mt][kt][0] = sm[r0 * A_QSTR + c];
            qf[mt][kt][1] = sm[(r0 + 8) * A_QSTR + c];
            qf[mt][kt][2] = sm[r0 * A_QSTR + c + 4];
            qf[mt][kt][3] = sm[(r0 + 8) * A_QSTR + c + 4];
        }

    float of[2][8][4];
#pragma unroll
    for (int mt = 0; mt < 2; mt++)
#pragma unroll
        for (int nt = 0; nt < 8; nt++)
#pragma unroll
            for (int e = 0; e < 4; e++) of[mt][nt][e] = 0.f;
    float mx[2][2]  = {{-1e30f, -1e30f}, {-1e30f, -1e30f}};
    float ell[2][2] = {{0.f, 0.f}, {0.f, 0.f}};

    uint32_t pw = A_POFF + warp * (32 * A_PSTR);

    for (int tj = 0; tj < T_; tj++) {
        if (tmask[(b * T_ + ti) * T_ + tj] == 0) continue;
#pragma unroll 1
        for (int half = 0; half < 2; half++) {
            int j0 = tj * S_ + half * 64;
            const float* kb = K + ((size_t)(b * NTOK + j0)) * INNER_ + h * DH_;
            const float* vb = V + ((size_t)(b * NTOK + j0)) * INNER_ + h * DH_;
            __syncthreads();     // previous chunk's reads done
            // K and V tiles: 64 rows x 16 float4-chunks = 1024 chunks EACH
#pragma unroll
            for (int i = 0; i < 8; i++) {
                int q = tid + i * 128;        // 0..1023
                int row = q >> 4, c4 = (q & 15) * 4;
                cp16(smBase + (uint32_t)(A_KOFF + row * A_KSTR + c4) * 4,
                     kb + (size_t)row * INNER_ + c4);
                cp16(smBase + (uint32_t)(A_VOFF + row * A_VSTR + c4) * 4,
                     vb + (size_t)row * INNER_ + c4);
            }
            cp_commit();
            cp_wait<0>();
            __syncthreads();

            // S = Q * K^T (32 rows x 64 keys per warp)
            float sf[2][8][4];
#pragma unroll
            for (int mt = 0; mt < 2; mt++)
#pragma unroll
                for (int nt = 0; nt < 8; nt++)
#pragma unroll
                    for (int e = 0; e < 4; e++) sf[mt][nt][e] = 0.f;

#pragma unroll
            for (int kt = 0; kt < 8; kt++) {
                uint32_t bfr[8][2];
#pragma unroll
                for (int nt = 0; nt < 8; nt++) {
                    int n = nt * 8 + (lane >> 2);
                    int c = kt * 8 + (lane & 3);
                    bfr[nt][0] = sm[A_KOFF + n * A_KSTR + c];
                    bfr[nt][1] = sm[A_KOFF + n * A_KSTR + c + 4];
                }
#pragma unroll
                for (int mt = 0; mt < 2; mt++)
#pragma unroll
                    for (int nt = 0; nt < 8; nt++)
                        mma_tf32(sf[mt][nt], qf[mt][kt], bfr[nt]);
            }

            // online softmax over 64 keys
#pragma unroll
            for (int mt = 0; mt < 2; mt++) {
#pragma unroll
                for (int hh = 0; hh < 2; hh++) {
                    float cm = -1e30f;
#pragma unroll
                    for (int nt = 0; nt < 8; nt++) {
                        float s0 = sf[mt][nt][2 * hh]     * 0.125f;
                        float s1 = sf[mt][nt][2 * hh + 1] * 0.125f;
                        sf[mt][nt][2 * hh]     = s0;
                        sf[mt][nt][2 * hh + 1] = s1;
                        cm = fmaxf(cm, fmaxf(s0, s1));
                    }
                    cm = fmaxf(cm, __shfl_xor_sync(0xffffffffu, cm, 1));
                    cm = fmaxf(cm, __shfl_xor_sync(0xffffffffu, cm, 2));
                    float nm = fmaxf(mx[mt][hh], cm);
                    float corr = __expf(mx[mt][hh] - nm);
                    mx[mt][hh] = nm;
                    ell[mt][hh] *= corr;
#pragma unroll
                    for (int nt = 0; nt < 8; nt++) {
                        of[mt][nt][2 * hh]     *= corr;
                        of[mt][nt][2 * hh + 1] *= corr;
                    }
                    float rs = 0.f;
                    int rloc = mt * 16 + (lane >> 2) + hh * 8;
#pragma unroll
                    for (int nt = 0; nt < 8; nt++) {
                        float p0 = __expf(sf[mt][nt][2 * hh]     - nm);
                        float p1 = __expf(sf[mt][nt][2 * hh + 1] - nm);
                        rs += p0 + p1;
                        *(uint2*)&sm[pw + rloc * A_PSTR + nt * 8 + 2 * (lane & 3)] =
                            make_uint2(f2tf32(p0), f2tf32(p1));
                    }
                    rs += __shfl_xor_sync(0xffffffffu, rs, 1);
                    rs += __shfl_xor_sync(0xffffffffu, rs, 2);
                    ell[mt][hh] += rs;
                }
            }
            __syncwarp();

            // O += P * V (P: 32x64, V: 64x64)
#pragma unroll
            for (int kt = 0; kt < 8; kt++) {
                uint32_t pf[2][4];
#pragma unroll
                for (int mt = 0; mt < 2; mt++) {
                    int r0 = mt * 16 + (lane >> 2);
                    int c  = kt * 8 + (lane & 3);
                    pf[mt][0] = sm[pw + r0 * A_PSTR + c];
                    pf[mt][1] = sm[pw + (r0 + 8) * A_PSTR + c];
                    pf[mt][2] = sm[pw + r0 * A_PSTR + c + 4];
                    pf[mt][3] = sm[pw + (r0 + 8) * A_PSTR + c + 4];
                }
                uint32_t vf[8][2];
#pragma unroll
                for (int nt = 0; nt < 8; nt++) {
                    int n = nt * 8 + (lane >> 2);
                    int k = kt * 8 + (lane & 3);
                    vf[nt][0] = sm[A_VOFF + k * A_VSTR + n];
                    vf[nt][1] = sm[A_VOFF + (k + 4) * A_VSTR + n];
                }
#pragma unroll
                for (int mt = 0; mt < 2; mt++)
#pragma unroll
                    for (int nt = 0; nt < 8; nt++)
                        mma_tf32(of[mt][nt], pf[mt], vf[nt]);
            }
            __syncwarp();
        }
    }

    // normalize + tf32-round + write
#pragma unroll
    for (int mt = 0; mt < 2; mt++) {
#pragma unroll
        for (int hh = 0; hh < 2; hh++) {
            float inv = (ell[mt][hh] > 0.f) ? (1.f / ell[mt][hh]) : 0.f;
            int row = b * NTOK + ti * S_ + warp * 32 + mt * 16 + (lane >> 2) + hh * 8;
#pragma unroll
            for (int nt = 0; nt < 8; nt++) {
                int col = h * DH_ + nt * 8 + 2 * (lane & 3);
                *(uint2*)(O + (size_t)row * INNER_ + col) =
                    make_uint2(f2tf32(of[mt][nt][2 * hh] * inv),
                               f2tf32(of[mt][nt][2 * hh + 1] * inv));
            }
        }
    }
}

// ---------------------------------------------------------------------------
// Gate: per row of P[4096,512]: g = sigmoid(dot(row, gate_w) + gate_b).
// ---------------------------------------------------------------------------
__global__ void __launch_bounds__(128) gate_kernel(
    const float* __restrict__ P, const float* __restrict__ gw,
    const float* __restrict__ gb, float* __restrict__ out)
{
    int m = blockIdx.x;
    int tid = threadIdx.x;
    const float* row = P + (size_t)m * D_;

    float v[4];
    float part = 0.f;
#pragma unroll
    for (int r = 0; r < 4; r++) {
        int j = tid + r * 128;
        v[r] = row[j];
        part += v[r] * gw[j];
    }
#pragma unroll
    for (int off = 16; off; off >>= 1)
        part += __shfl_xor_sync(0xffffffffu, part, off);

    __shared__ float red[4];
    if ((tid & 31) == 0) red[tid >> 5] = part;
    __syncthreads();
    float tot = red[0] + red[1] + red[2] + red[3] + gb[0];
    float gate = 1.f / (1.f + __expf(-tot));

    float* orow = out + (size_t)m * D_;
#pragma unroll
    for (int r = 0; r < 4; r++) {
        int j = tid + r * 128;
        orow[j] = v[r] * gate;
    }
}

// ---------------------------------------------------------------------------
extern "C" void kernel_launch(void* const* d_in, const int* in_sizes, int n_in,
                              void* d_out, int out_size)
{
    (void)in_sizes; (void)n_in; (void)out_size;
    const float* x     = (const float*)d_in[0];
    const float* y     = (const float*)d_in[1];
    const int*   tmask = (const int*)  d_in[2];
    const float* Wq    = (const float*)d_in[3];
    const float* Wk    = (const float*)d_in[4];
    const float* Wv    = (const float*)d_in[5];
    const float* Wo    = (const float*)d_in[6];
    const float* bo    = (const float*)d_in[7];
    const float* pos   = (const float*)d_in[8];
    const float* gw    = (const float*)d_in[9];
    const float* gb    = (const float*)d_in[10];
    float* out = (float*)d_out;

    float *Qp, *Kp, *Vp, *Op, *Pp, *Wc;
    float2* ropeTab;
    cudaGetSymbolAddress((void**)&Qp, g_Q);
    cudaGetSymbolAddress((void**)&Kp, g_K);
    cudaGetSymbolAddress((void**)&Vp, g_V);
    cudaGetSymbolAddress((void**)&Op, g_O);
    cudaGetSymbolAddress((void**)&Pp, g_P);
    cudaGetSymbolAddress((void**)&Wc, g_W);
    cudaGetSymbolAddress((void**)&ropeTab, g_rope);

    cudaFuncSetAttribute(gemm3_kernel<D_, INNER_, 0>,
                         cudaFuncAttributeMaxDynamicSharedMemorySize, G_SMEM_BYTES);
    cudaFuncSetAttribute(gemm3_kernel<INNER_, D_, 1>,
                         cudaFuncAttributeMaxDynamicSharedMemorySize, G_SMEM_BYTES);
    cudaFuncSetAttribute(attn_mma_kernel,
                         cudaFuncAttributeMaxDynamicSharedMemorySize, A_SMEM_BYTES);

    prep_xy_kernel<<<HALF_XY / 256, 256>>>(x, y, pos, Op, Op + HALF_XY);
    prep_w_kernel<<<(4 * WSEG) / 256, 256>>>(Wq, Wk, Wv, Wo, Wc);
    prep_rope_kernel<<<(NTOK * 32) / 256, 256>>>(ropeTab);

    // QKV (+fused table RoPE on Q/K): [4096,1024] = xp/yp @ Wq/Wk/Wv
    dim3 gq(INNER_ / 128, MROWS / 128, 3);     // 8 x 32 x 3
    gemm3_kernel<D_, INNER_, 0><<<gq, 128, G_SMEM_BYTES>>>(
        Op, Wc, Qp, Kp, Vp, nullptr, ropeTab);

    attn_mma_kernel<<<B_ * H_ * T_, 128, A_SMEM_BYTES>>>(Qp, Kp, Vp, tmask, Op);

    // Proj: P[4096,512] = O @ Wo + bo
    dim3 gp(D_ / 128, MROWS / 128, 1);         // 4 x 32
    gemm3_kernel<INNER_, D_, 1><<<gp, 128, G_SMEM_BYTES>>>(
        Op, Wc + 3 * WSEG, Pp, nullptr, nullptr, bo, nullptr);

    gate_kernel<<<MROWS, 128>>>(Pp, gw, gb, out);
}

// round 17
// speedup vs baseline: 1.1909x; 1.1666x over previous
#include <cuda_runtime.h>
#include <cuda_fp16.h>
#include <math.h>
#include <stdint.h>

// Problem constants
#define B_     2
#define T_     16
#define S_     128
#define D_     512
#define H_     16
#define DH_    64
#define INNER_ 1024
#define NTOK   2048    // T_*S_
#define MROWS  4096    // B_*NTOK
#define HALF_XY 2097152   // MROWS*D_ elements per x/y plane
#define WSEG    524288    // elements per weight matrix

// Scratch (device globals)
__device__ float g_Q[MROWS * INNER_];
__device__ float g_K[MROWS * INNER_];
__device__ float g_V[MROWS * INNER_];
__device__ __half g_A16[2 * HALF_XY];      // fp16 x+pos | y+pos, [m][k]
__device__ __half g_Wt16[4 * WSEG];        // fp16 TRANSPOSED weights [N][K]
__device__ __half g_O16[MROWS * INNER_];   // fp16 attention output
__device__ float g_P[MROWS * D_];          // proj output
__device__ float2 g_rope[NTOK * 32];       // (cos,sin) per (pos, freq)

// ---------------------------------------------------------------------------
// helpers
// ---------------------------------------------------------------------------
__device__ __forceinline__ uint32_t f2tf32(float f) {
    uint32_t u;
    asm("cvt.rna.tf32.f32 %0, %1;" : "=r"(u) : "f"(f));
    return u;
}

__device__ __forceinline__ void mma_tf32(float* c, const uint32_t* a,
                                         const uint32_t* b) {
    asm volatile(
        "mma.sync.aligned.m16n8k8.row.col.f32.tf32.tf32.f32 "
        "{%0,%1,%2,%3},{%4,%5,%6,%7},{%8,%9},{%0,%1,%2,%3};"
        : "+f"(c[0]), "+f"(c[1]), "+f"(c[2]), "+f"(c[3])
        : "r"(a[0]), "r"(a[1]), "r"(a[2]), "r"(a[3]), "r"(b[0]), "r"(b[1]));
}

__device__ __forceinline__ void mma_f16(float* c, const uint32_t* a,
                                        const uint32_t* b) {
    asm volatile(
        "mma.sync.aligned.m16n8k16.row.col.f32.f16.f16.f32 "
        "{%0,%1,%2,%3},{%4,%5,%6,%7},{%8,%9},{%0,%1,%2,%3};"
        : "+f"(c[0]), "+f"(c[1]), "+f"(c[2]), "+f"(c[3])
        : "r"(a[0]), "r"(a[1]), "r"(a[2]), "r"(a[3]), "r"(b[0]), "r"(b[1]));
}

__device__ __forceinline__ void cp16(uint32_t dst, const void* src) {
    asm volatile("cp.async.cg.shared.global [%0], [%1], 16;" :: "r"(dst), "l"(src));
}
__device__ __forceinline__ void cp_commit() {
    asm volatile("cp.async.commit_group;");
}
template<int N> __device__ __forceinline__ void cp_wait() {
    asm volatile("cp.async.wait_group %0;" :: "n"(N));
}

#define ROPE_C (13.287712379549449f / 32.0f)

// ---------------------------------------------------------------------------
// prep kernels
// ---------------------------------------------------------------------------
__global__ void __launch_bounds__(256) prep_xy16_kernel(
    const float* __restrict__ x, const float* __restrict__ y,
    const float* __restrict__ pos, __half* __restrict__ A16)
{
    int i = blockIdx.x * blockDim.x + threadIdx.x;
    int m = i >> 9;
    int d = i & 511;
    int t = (m & (NTOK - 1)) >> 7;
    float p = pos[t * D_ + d];
    A16[i]           = __float2half_rn(x[i] + p);
    A16[HALF_XY + i] = __float2half_rn(y[i] + p);
}

// transpose W[K,N] -> Wt[N,K] fp16. grid (32,32,4), block (32,8).
__global__ void __launch_bounds__(256) prep_wt16_kernel(
    const float* __restrict__ Wq, const float* __restrict__ Wk,
    const float* __restrict__ Wv, const float* __restrict__ Wo,
    __half* __restrict__ Wt)
{
    int z = blockIdx.z;
    int Kz = (z < 3) ? D_ : INNER_;
    int Nz = (z < 3) ? INNER_ : D_;
    int nb = blockIdx.x * 32, kb = blockIdx.y * 32;
    if (nb >= Nz || kb >= Kz) return;
    const float* W = (z == 0) ? Wq : (z == 1) ? Wk : (z == 2) ? Wv : Wo;

    __shared__ float t[32][33];
#pragma unroll
    for (int r = 0; r < 4; r++) {
        int k = kb + threadIdx.y + r * 8;
        t[threadIdx.y + r * 8][threadIdx.x] = W[(size_t)k * Nz + nb + threadIdx.x];
    }
    __syncthreads();
#pragma unroll
    for (int r = 0; r < 4; r++) {
        int n = nb + threadIdx.y + r * 8;
        int k = kb + threadIdx.x;
        Wt[(size_t)z * WSEG + (size_t)n * Kz + k] =
            __float2half_rn(t[threadIdx.x][threadIdx.y + r * 8]);
    }
}

// rope table: (cos,sin) for position i, freq dd
__global__ void __launch_bounds__(256) prep_rope_kernel(float2* __restrict__ tab)
{
    int idx = blockIdx.x * blockDim.x + threadIdx.x;   // [0, NTOK*32)
    int i  = idx >> 5;
    int dd = idx & 31;
    float inv = exp2f(-(float)dd * ROPE_C);
    float f = (float)i * inv;
    tab[idx] = make_float2(cosf(f), sinf(f));
}

// ---------------------------------------------------------------------------
// fp16 GEMM: CTA 128x128, 4 warps of 64x64, BK=32 (2 x k16 steps), 2-stage
// cp.async. A [M][K] fp16, W pre-transposed [N][K] fp16 (k-contiguous so the
// fp16 B fragment's k-pairs are packed in one b32).
// MODE 0 (qkv): z selects input/weight/output. z<2: fused table-RoPE then
//   tf32-rounded store. z=2 (V): tf32-rounded store.  (attention reads fp32)
// MODE 1 (proj): acc + bias -> g_P (fp32).
// smem (u32 words): A0@0, A1@2560, B0@5120, B1@7680; stride 20/row.
// ---------------------------------------------------------------------------
#define F_ASTR 20
#define F_A0   0
#define F_A1   2560
#define F_B0   5120
#define F_B1   7680
#define F_SMEM_BYTES (10240 * 4)

template<int KDIM, int NDIM, int MODE>
__global__ void __launch_bounds__(128, 2) gemm6_kernel(
    const __half* __restrict__ Abase, const __half* __restrict__ Wtbase,
    float* __restrict__ C0, float* __restrict__ C1, float* __restrict__ C2,
    const float* __restrict__ bias, const float2* __restrict__ rope)
{
    extern __shared__ uint32_t dsm[];

    const __half* A;
    const __half* W;
    float* C;
    int z = 0;
    if (MODE == 0) {
        z = blockIdx.z;
        A = Abase + ((z == 2) ? HALF_XY : 0);
        W = Wtbase + (size_t)z * WSEG;
        C = (z == 0) ? C0 : (z == 1) ? C1 : C2;
    } else {
        A = Abase; W = Wtbase + (size_t)3 * WSEG; C = C0;
    }

    int tid   = threadIdx.x;
    int lane  = tid & 31;
    int warp  = tid >> 5;
    int warpM = warp >> 1;
    int warpN = warp & 1;
    int m0 = blockIdx.y * 128;
    int n0 = blockIdx.x * 128;

    uint32_t smBase = (uint32_t)__cvta_generic_to_shared(dsm);
    uint32_t aOff[2] = {smBase + F_A0 * 4, smBase + F_A1 * 4};
    uint32_t bOff[2] = {smBase + F_B0 * 4, smBase + F_B1 * 4};

    const int NS = KDIM / 32;

    // slab: A 128 rows x 32 fp16 (4 x 16B chunks/row); B same on Wt rows.
    auto load_slab = [&](int s, int buf) {
#pragma unroll
        for (int i = 0; i < 4; i++) {
            int q = tid + i * 128;            // 0..511
            int row = q >> 2, ch = q & 3;
            cp16(aOff[buf] + (uint32_t)(row * F_ASTR + ch * 4) * 4,
                 A + (size_t)(m0 + row) * KDIM + s * 32 + ch * 8);
            cp16(bOff[buf] + (uint32_t)(row * F_ASTR + ch * 4) * 4,
                 W + (size_t)(n0 + row) * KDIM + s * 32 + ch * 8);
        }
        cp_commit();
    };

    float acc[4][8][4];
#pragma unroll
    for (int mt = 0; mt < 4; mt++)
#pragma unroll
        for (int nt = 0; nt < 8; nt++)
#pragma unroll
            for (int e = 0; e < 4; e++) acc[mt][nt][e] = 0.f;

    load_slab(0, 0);

    for (int s = 0; s < NS; s++) {
        int buf = s & 1;
        if (s + 1 < NS) {
            load_slab(s + 1, buf ^ 1);
            cp_wait<1>();
        } else {
            cp_wait<0>();
        }
        __syncthreads();

        const uint32_t* uA = dsm + (buf ? F_A1 : F_A0);
        const uint32_t* uB = dsm + (buf ? F_B1 : F_B0);
#pragma unroll
        for (int ks = 0; ks < 2; ks++) {
            uint32_t af[4][4];
#pragma unroll
            for (int mt = 0; mt < 4; mt++) {
                int r0 = warpM * 64 + mt * 16 + (lane >> 2);
                int k2 = ks * 8 + (lane & 3);
                af[mt][0] = uA[r0 * F_ASTR + k2];
                af[mt][1] = uA[(r0 + 8) * F_ASTR + k2];
                af[mt][2] = uA[r0 * F_ASTR + k2 + 4];
                af[mt][3] = uA[(r0 + 8) * F_ASTR + k2 + 4];
            }
            uint32_t bf[8][2];
#pragma unroll
            for (int nt = 0; nt < 8; nt++) {
                int n = warpN * 64 + nt * 8 + (lane >> 2);
                int k2 = ks * 8 + (lane & 3);
                bf[nt][0] = uB[n * F_ASTR + k2];
                bf[nt][1] = uB[n * F_ASTR + k2 + 4];
            }
#pragma unroll
            for (int mt = 0; mt < 4; mt++)
#pragma unroll
                for (int nt = 0; nt < 8; nt++)
                    mma_f16(acc[mt][nt], af[mt], bf[nt]);
        }
        __syncthreads();
    }

    // ---- fused table-RoPE for Q/K (z<2). Column d pairs with d+32 =
    // acc[mt][nt+4]; values from the rope table. Mapping validated R10/R16.
    if (MODE == 0 && z < 2) {
#pragma unroll
        for (int mt = 0; mt < 4; mt++) {
            int row = m0 + warpM * 64 + mt * 16 + (lane >> 2);
            int i0 = row & (NTOK - 1);
            int i1 = (row + 8) & (NTOK - 1);
#pragma unroll
            for (int nt = 0; nt < 4; nt++) {
                int d0 = nt * 8 + 2 * (lane & 3);
                float4 cs0 = *(const float4*)&rope[i0 * 32 + d0]; // c0,s0,c1,s1
                float4 cs1 = *(const float4*)&rope[i1 * 32 + d0];
                float a, bb;
                a = acc[mt][nt][0]; bb = acc[mt][nt + 4][0];
                acc[mt][nt][0]     = a * cs0.x - bb * cs0.y;
                acc[mt][nt + 4][0] = bb * cs0.x + a * cs0.y;
                a = acc[mt][nt][1]; bb = acc[mt][nt + 4][1];
                acc[mt][nt][1]     = a * cs0.z - bb * cs0.w;
                acc[mt][nt + 4][1] = bb * cs0.z + a * cs0.w;
                a = acc[mt][nt][2]; bb = acc[mt][nt + 4][2];
                acc[mt][nt][2]     = a * cs1.x - bb * cs1.y;
                acc[mt][nt + 4][2] = bb * cs1.x + a * cs1.y;
                a = acc[mt][nt][3]; bb = acc[mt][nt + 4][3];
                acc[mt][nt][3]     = a * cs1.z - bb * cs1.w;
                acc[mt][nt + 4][3] = bb * cs1.z + a * cs1.w;
            }
        }
    }

#pragma unroll
    for (int mt = 0; mt < 4; mt++) {
#pragma unroll
        for (int nt = 0; nt < 8; nt++) {
            int row = m0 + warpM * 64 + mt * 16 + (lane >> 2);
            int col = n0 + warpN * 64 + nt * 8 + 2 * (lane & 3);
            if (MODE == 1) {
                float b0 = bias[col], b1 = bias[col + 1];
                *(float2*)(C + (size_t)row * NDIM + col) =
                    make_float2(acc[mt][nt][0] + b0, acc[mt][nt][1] + b1);
                *(float2*)(C + (size_t)(row + 8) * NDIM + col) =
                    make_float2(acc[mt][nt][2] + b0, acc[mt][nt][3] + b1);
            } else {
                // Q/K (rotated) and V stored tf32-rounded for the attn mma
                *(uint2*)(C + (size_t)row * NDIM + col) =
                    make_uint2(f2tf32(acc[mt][nt][0]), f2tf32(acc[mt][nt][1]));
                *(uint2*)(C + (size_t)(row + 8) * NDIM + col) =
                    make_uint2(f2tf32(acc[mt][nt][2]), f2tf32(acc[mt][nt][3]));
            }
        }
    }
}

// ---------------------------------------------------------------------------
// Flash attention (tf32 core, unchanged): 64-key chunks, cp.async K/V loads.
// Epilogue writes fp16 O for the fp16 proj GEMM.
// ---------------------------------------------------------------------------
#define A_KOFF 0
#define A_VOFF 4352
#define A_POFF 8960
#define A_KSTR 68
#define A_VSTR 72
#define A_PSTR 68
#define A_QSTR 68
#define A_SMEM_BYTES (17664 * 4)

__global__ void __launch_bounds__(128, 2) attn_mma_kernel(
    const float* __restrict__ Q, const float* __restrict__ K,
    const float* __restrict__ V, const int* __restrict__ tmask,
    __half* __restrict__ O16)
{
    extern __shared__ uint32_t sm[];

    int blk  = blockIdx.x;
    int ti   = blk % T_;
    int bh   = blk / T_;
    int h    = bh % H_;
    int b    = bh / H_;
    int tid  = threadIdx.x;
    int lane = tid & 31;
    int warp = tid >> 5;

    uint32_t smBase = (uint32_t)__cvta_generic_to_shared(sm);

    // stage Q tile 128x64 (raw bits already tf32)
    {
        const float* qg = Q + ((size_t)(b * NTOK + ti * S_)) * INNER_ + h * DH_;
#pragma unroll
        for (int i = 0; i < 16; i++) {
            int idx = tid + i * 128;
            int row = idx >> 4, c4 = (idx & 15) * 4;
            float4 v4 = *(const float4*)(qg + (size_t)row * INNER_ + c4);
            *(uint4*)&sm[row * A_QSTR + c4] =
                make_uint4(__float_as_uint(v4.x), __float_as_uint(v4.y),
                           __float_as_uint(v4.z), __float_as_uint(v4.w));
        }
    }
    __syncthreads();

    uint32_t qf[2][8][4];
#pragma unroll
    for (int mt = 0; mt < 2; mt++)
#pragma unroll
        for (int kt = 0; kt < 8; kt++) {
            int r0 = warp * 32 + mt * 16 + (lane >> 2);
            int c  = kt * 8 + (lane & 3);
            qf[mt][kt][0] = sm[r0 * A_QSTR + c];
            qf[mt][kt][1] = sm[(r0 + 8) * A_QSTR + c];
            qf[mt][kt][2] = sm[r0 * A_QSTR + c + 4];
            qf[mt][kt][3] = sm[(r0 + 8) * A_QSTR + c + 4];
        }

    float of[2][8][4];
#pragma unroll
    for (int mt = 0; mt < 2; mt++)
#pragma unroll
        for (int nt = 0; nt < 8; nt++)
#pragma unroll
            for (int e = 0; e < 4; e++) of[mt][nt][e] = 0.f;
    float mx[2][2]  = {{-1e30f, -1e30f}, {-1e30f, -1e30f}};
    float ell[2][2] = {{0.f, 0.f}, {0.f, 0.f}};

    uint32_t pw = A_POFF + warp * (32 * A_PSTR);

    for (int tj = 0; tj < T_; tj++) {
        if (tmask[(b * T_ + ti) * T_ + tj] == 0) continue;
#pragma unroll 1
        for (int half = 0; half < 2; half++) {
            int j0 = tj * S_ + half * 64;
            const float* kb = K + ((size_t)(b * NTOK + j0)) * INNER_ + h * DH_;
            const float* vb = V + ((size_t)(b * NTOK + j0)) * INNER_ + h * DH_;
            __syncthreads();
#pragma unroll
            for (int i = 0; i < 8; i++) {
                int q = tid + i * 128;
                int row = q >> 4, c4 = (q & 15) * 4;
                cp16(smBase + (uint32_t)(A_KOFF + row * A_KSTR + c4) * 4,
                     kb + (size_t)row * INNER_ + c4);
                cp16(smBase + (uint32_t)(A_VOFF + row * A_VSTR + c4) * 4,
                     vb + (size_t)row * INNER_ + c4);
            }
            cp_commit();
            cp_wait<0>();
            __syncthreads();

            float sf[2][8][4];
#pragma unroll
            for (int mt = 0; mt < 2; mt++)
#pragma unroll
                for (int nt = 0; nt < 8; nt++)
#pragma unroll
                    for (int e = 0; e < 4; e++) sf[mt][nt][e] = 0.f;

#pragma unroll
            for (int kt = 0; kt < 8; kt++) {
                uint32_t bfr[8][2];
#pragma unroll
                for (int nt = 0; nt < 8; nt++) {
                    int n = nt * 8 + (lane >> 2);
                    int c = kt * 8 + (lane & 3);
                    bfr[nt][0] = sm[A_KOFF + n * A_KSTR + c];
                    bfr[nt][1] = sm[A_KOFF + n * A_KSTR + c + 4];
                }
#pragma unroll
                for (int mt = 0; mt < 2; mt++)
#pragma unroll
                    for (int nt = 0; nt < 8; nt++)
                        mma_tf32(sf[mt][nt], qf[mt][kt], bfr[nt]);
            }

#pragma unroll
            for (int mt = 0; mt < 2; mt++) {
#pragma unroll
                for (int hh = 0; hh < 2; hh++) {
                    float cm = -1e30f;
#pragma unroll
                    for (int nt = 0; nt < 8; nt++) {
                        float s0 = sf[mt][nt][2 * hh]     * 0.125f;
                        float s1 = sf[mt][nt][2 * hh + 1] * 0.125f;
                        sf[mt][nt][2 * hh]     = s0;
                        sf[mt][nt][2 * hh + 1] = s1;
                        cm = fmaxf(cm, fmaxf(s0, s1));
                    }
                    cm = fmaxf(cm, __shfl_xor_sync(0xffffffffu, cm, 1));
                    cm = fmaxf(cm, __shfl_xor_sync(0xffffffffu, cm, 2));
                    float nm = fmaxf(mx[mt][hh], cm);
                    float corr = __expf(mx[mt][hh] - nm);
                    mx[mt][hh] = nm;
                    ell[mt][hh] *= corr;
#pragma unroll
                    for (int nt = 0; nt < 8; nt++) {
                        of[mt][nt][2 * hh]     *= corr;
                        of[mt][nt][2 * hh + 1] *= corr;
                    }
                    float rs = 0.f;
                    int rloc = mt * 16 + (lane >> 2) + hh * 8;
#pragma unroll
                    for (int nt = 0; nt < 8; nt++) {
                        float p0 = __expf(sf[mt][nt][2 * hh]     - nm);
                        float p1 = __expf(sf[mt][nt][2 * hh + 1] - nm);
                        rs += p0 + p1;
                        *(uint2*)&sm[pw + rloc * A_PSTR + nt * 8 + 2 * (lane & 3)] =
                            make_uint2(f2tf32(p0), f2tf32(p1));
                    }
                    rs += __shfl_xor_sync(0xffffffffu, rs, 1);
                    rs += __shfl_xor_sync(0xffffffffu, rs, 2);
                    ell[mt][hh] += rs;
                }
            }
            __syncwarp();

#pragma unroll
            for (int kt = 0; kt < 8; kt++) {
                uint32_t pf[2][4];
#pragma unroll
                for (int mt = 0; mt < 2; mt++) {
                    int r0 = mt * 16 + (lane >> 2);
                    int c  = kt * 8 + (lane & 3);
                    pf[mt][0] = sm[pw + r0 * A_PSTR + c];
                    pf[mt][1] = sm[pw + (r0 + 8) * A_PSTR + c];
                    pf[mt][2] = sm[pw + r0 * A_PSTR + c + 4];
                    pf[mt][3] = sm[pw + (r0 + 8) * A_PSTR + c + 4];
                }
                uint32_t vf[8][2];
#pragma unroll
                for (int nt = 0; nt < 8; nt++) {
                    int n = nt * 8 + (lane >> 2);
                    int k = kt * 8 + (lane & 3);
                    vf[nt][0] = sm[A_VOFF + k * A_VSTR + n];
                    vf[nt][1] = sm[A_VOFF + (k + 4) * A_VSTR + n];
                }
#pragma unroll
                for (int mt = 0; mt < 2; mt++)
#pragma unroll
                    for (int nt = 0; nt < 8; nt++)
                        mma_tf32(of[mt][nt], pf[mt], vf[nt]);
            }
            __syncwarp();
        }
    }

    // normalize + fp16 write (proj consumes fp16; same 10-bit mantissa)
#pragma unroll
    for (int mt = 0; mt < 2; mt++) {
#pragma unroll
        for (int hh = 0; hh < 2; hh++) {
            float inv = (ell[mt][hh] > 0.f) ? (1.f / ell[mt][hh]) : 0.f;
            int row = b * NTOK + ti * S_ + warp * 32 + mt * 16 + (lane >> 2) + hh * 8;
#pragma unroll
            for (int nt = 0; nt < 8; nt++) {
                int col = h * DH_ + nt * 8 + 2 * (lane & 3);
                __half2 hp = __floats2half2_rn(of[mt][nt][2 * hh] * inv,
                                               of[mt][nt][2 * hh + 1] * inv);
                *(__half2*)(O16 + (size_t)row * INNER_ + col) = hp;
            }
        }
    }
}

// ---------------------------------------------------------------------------
// Gate: per row of P[4096,512]: g = sigmoid(dot(row, gate_w) + gate_b).
// ---------------------------------------------------------------------------
__global__ void __launch_bounds__(128) gate_kernel(
    const float* __restrict__ P, const float* __restrict__ gw,
    const float* __restrict__ gb, float* __restrict__ out)
{
    int m = blockIdx.x;
    int tid = threadIdx.x;
    const float* row = P + (size_t)m * D_;

    float v[4];
    float part = 0.f;
#pragma unroll
    for (int r = 0; r < 4; r++) {
        int j = tid + r * 128;
        v[r] = row[j];
        part += v[r] * gw[j];
    }
#pragma unroll
    for (int off = 16; off; off >>= 1)
        part += __shfl_xor_sync(0xffffffffu, part, off);

    __shared__ float red[4];
    if ((tid & 31) == 0) red[tid >> 5] = part;
    __syncthreads();
    float tot = red[0] + red[1] + red[2] + red[3] + gb[0];
    float gate = 1.f / (1.f + __expf(-tot));

    float* orow = out + (size_t)m * D_;
#pragma unroll
    for (int r = 0; r < 4; r++) {
        int j = tid + r * 128;
        orow[j] = v[r] * gate;
    }
}

// ---------------------------------------------------------------------------
extern "C" void kernel_launch(void* const* d_in, const int* in_sizes, int n_in,
                              void* d_out, int out_size)
{
    (void)in_sizes; (void)n_in; (void)out_size;
    const float* x     = (const float*)d_in[0];
    const float* y     = (const float*)d_in[1];
    const int*   tmask = (const int*)  d_in[2];
    const float* Wq    = (const float*)d_in[3];
    const float* Wk    = (const float*)d_in[4];
    const float* Wv    = (const float*)d_in[5];
    const float* Wo    = (const float*)d_in[6];
    const float* bo    = (const float*)d_in[7];
    const float* pos   = (const float*)d_in[8];
    const float* gw    = (const float*)d_in[9];
    const float* gb    = (const float*)d_in[10];
    float* out = (float*)d_out;

    float *Qp, *Kp, *Vp, *Pp;
    __half *A16, *Wt16, *O16;
    float2* ropeTab;
    cudaGetSymbolAddress((void**)&Qp, g_Q);
    cudaGetSymbolAddress((void**)&Kp, g_K);
    cudaGetSymbolAddress((void**)&Vp, g_V);
    cudaGetSymbolAddress((void**)&A16, g_A16);
    cudaGetSymbolAddress((void**)&Wt16, g_Wt16);
    cudaGetSymbolAddress((void**)&O16, g_O16);
    cudaGetSymbolAddress((void**)&Pp, g_P);
    cudaGetSymbolAddress((void**)&ropeTab, g_rope);

    cudaFuncSetAttribute(gemm6_kernel<D_, INNER_, 0>,
                         cudaFuncAttributeMaxDynamicSharedMemorySize, F_SMEM_BYTES);
    cudaFuncSetAttribute(gemm6_kernel<INNER_, D_, 1>,
                         cudaFuncAttributeMaxDynamicSharedMemorySize, F_SMEM_BYTES);
    cudaFuncSetAttribute(attn_mma_kernel,
                         cudaFuncAttributeMaxDynamicSharedMemorySize, A_SMEM_BYTES);

    prep_xy16_kernel<<<HALF_XY / 256, 256>>>(x, y, pos, A16);
    prep_wt16_kernel<<<dim3(32, 32, 4), dim3(32, 8)>>>(Wq, Wk, Wv, Wo, Wt16);
    prep_rope_kernel<<<(NTOK * 32) / 256, 256>>>(ropeTab);

    // QKV fp16 (+fused table RoPE on Q/K): [4096,1024] = (x/y+pos) @ W
    dim3 gq(INNER_ / 128, MROWS / 128, 3);     // 8 x 32 x 3
    gemm6_kernel<D_, INNER_, 0><<<gq, 128, F_SMEM_BYTES>>>(
        A16, Wt16, Qp, Kp, Vp, nullptr, ropeTab);

    attn_mma_kernel<<<B_ * H_ * T_, 128, A_SMEM_BYTES>>>(Qp, Kp, Vp, tmask, O16);

    // Proj fp16: P[4096,512] = O @ Wo + bo
    dim3 gp(D_ / 128, MROWS / 128, 1);         // 4 x 32
    gemm6_kernel<INNER_, D_, 1><<<gp, 128, F_SMEM_BYTES>>>(
        O16, Wt16, Pp, nullptr, nullptr, bo, nullptr);

    gate_kernel<<<MROWS, 128>>>(Pp, gw, gb, out);
}